// round 15
// baseline (speedup 1.0000x reference)
#include <cuda_runtime.h>
#include <math.h>

#if defined(__CUDA_ARCH_FEAT_SM103_ALL) || defined(__CUDA_ARCH_FEAT_SM100_ALL) || defined(__CUDA_ARCH_SPECIFIC__)
#define F32X2_OK 1
#else
#define F32X2_OK 0
#endif

#define BB 256
#define TT 512
#define II 256
#define HH 512
#define AA 18
#define KK 768
#define NCTA 128
#define NS 4            // k slices of 192
#define KS 192
#define JT 128          // cols per CTA
#define RT 32           // rows per CTA

// ---------------- scratch (static device globals; no allocation) ----------------
__device__ float g_W[(size_t)KK * HH];       // [k][j] k<512 -> W_hh[j][k], else W_ih[j][k-512]
__device__ float g_bias[HH];
__device__ float g_part[NS][BB][HH];         // per-slice partials (single-buffered, barrier-ordered)
__device__ float g_hcur[BB][HH];             // current h (sorted-row index)
__device__ float g_hout[(size_t)BB * TT * HH];
__device__ int   g_perm[BB];
__device__ int   g_active[TT];
__device__ int   g_count, g_gen;

// ---------------- cp.async ----------------
__device__ __forceinline__ void cpa16(void* sdst, const void* gsrc) {
    unsigned s = (unsigned)__cvta_generic_to_shared(sdst);
    asm volatile("cp.async.cg.shared.global [%0], [%1], 16;\n" :: "r"(s), "l"(gsrc));
}
#define CPA_COMMIT() asm volatile("cp.async.commit_group;\n" ::: "memory")
#define CPA_WAIT0()  asm volatile("cp.async.wait_group 0;\n" ::: "memory")

// ---------------- f32x2 packed FMA (sm_103a pass only) ----------------
#if F32X2_OK
__device__ __forceinline__ void fma2(unsigned long long& d, unsigned long long a, unsigned long long b) {
    asm("fma.rn.f32x2 %0, %1, %2, %0;" : "+l"(d) : "l"(a), "l"(b));
}
__device__ __forceinline__ unsigned long long packdup(float h) {
    unsigned long long r;
    unsigned hb = __float_as_uint(h);
    asm("mov.b64 %0, {%1, %1};" : "=l"(r) : "r"(hb));
    return r;
}
__device__ __forceinline__ void unpack2(unsigned long long v, float& lo, float& hi) {
    unsigned a, b;
    asm("mov.b64 {%0, %1}, %2;" : "=r"(a), "=r"(b) : "l"(v));
    lo = __uint_as_float(a); hi = __uint_as_float(b);
}
#endif

// ---------------- grid barrier (128 CTAs, co-residency guaranteed) ----------------
__device__ __forceinline__ void gsync(int target) {
    __syncthreads();
    if (threadIdx.x == 0) {
        __threadfence();
        int a = atomicAdd(&g_count, 1);
        if (a == NCTA * target - 1) atomicExch(&g_gen, target);
        else { while (*((volatile int*)&g_gen) < target) {} __threadfence(); }
    }
    __syncthreads();
}

// ---------------- prep: counting sort by length (desc) + active counts + barrier reset ----------------
__global__ void prep_sort(const int* __restrict__ lengths) {
    __shared__ int s_len[BB];
    __shared__ int s_hist[TT + 1];
    __shared__ int s_S[TT + 1];
    __shared__ int s_base[TT + 1];
    int tid = threadIdx.x;          // 512 threads
    if (tid == 0) { g_count = 0; g_gen = 0; }
    if (tid < BB) s_len[tid] = lengths[tid];
    for (int i = tid; i <= TT; i += blockDim.x) s_hist[i] = 0;
    __syncthreads();
    if (tid < BB) atomicAdd(&s_hist[s_len[tid]], 1);
    __syncthreads();
    if (tid == 0) {
        s_S[TT] = 0;
        for (int v = TT - 1; v >= 0; --v) s_S[v] = s_S[v + 1] + s_hist[v + 1];
    }
    __syncthreads();
    for (int i = tid; i <= TT; i += blockDim.x) s_base[i] = s_S[i];
    if (tid < TT) g_active[tid] = s_S[tid];
    __syncthreads();
    if (tid < BB) {
        int pos = atomicAdd(&s_base[s_len[tid]], 1);
        g_perm[pos] = tid;
    }
}

// ---------------- prep: pack W concat k-major, bias ----------------
__global__ void prep_pack(const float* __restrict__ W_ih, const float* __restrict__ W_hh,
                          const float* __restrict__ b_ih, const float* __restrict__ b_hh) {
    int idx = blockIdx.x * blockDim.x + threadIdx.x;
    int stride = gridDim.x * blockDim.x;
    for (int i = idx; i < KK * HH; i += stride) {
        int k = i / HH, j = i % HH;
        g_W[i] = (k < HH) ? W_hh[(size_t)j * HH + k] : W_ih[(size_t)j * II + (k - HH)];
    }
    for (int i = idx; i < HH; i += stride) g_bias[i] = b_ih[i] + b_hh[i];
}

// ---------------- persistent RNN: 128 CTAs, W stationary in smem ----------------
// cta -> cg(4 col groups of 128) x rg(8 row groups of 32) x z(4 k-slices of 192)
__global__ __launch_bounds__(256, 1) void rnn_persist(const float* __restrict__ x,
                                                      const float* __restrict__ h0) {
    extern __shared__ char smem_raw[];
    float* s_h = (float*)smem_raw;                       // 32*192*4 = 24576 B
    float (*s_w)[JT] = (float (*)[JT])(smem_raw + RT * KS * 4);   // 192*128*4 = 98304 B
    __shared__ int s_b[RT];

    int cta = blockIdx.x;
    int tid = threadIdx.x;
    int cg = cta & 3;
    int rg = (cta >> 2) & 7;
    int z  = cta >> 5;
    int j0 = cg * JT;
    int r0 = rg * RT;

    // stationary W slice -> smem (6144 float4, 24/thread)
    {
        const float* gw = g_W + (size_t)(z * KS) * HH + j0;
        #pragma unroll
        for (int q = 0; q < 24; ++q) {
            int p  = tid + q * 256;
            int kk = p >> 5;
            int jj = (p & 31) * 4;
            cpa16(&s_w[kk][jj], gw + (size_t)kk * HH + jj);
        }
        CPA_COMMIT();
    }
    if (tid < RT) s_b[tid] = g_perm[r0 + tid];
    CPA_WAIT0();
    __syncthreads();

    int ty = tid >> 5;          // 0..7 (row group of 4)
    int tx = tid & 31;          // 0..31 (col group of 4)
    int cb = tx * 4;
    int bar = 0;

    // phase-A identity for this thread: r = cta*2 + (tid>=128), j4 = (tid&127)*4
    int pa_r  = cta * 2 + (tid >> 7);
    int pa_j4 = (tid & 127) * 4;
    int pa_b  = g_perm[pa_r];

    for (int t = 0; t <= TT; ++t) {
        // ---- phase A: finalize h_{t-1} once, globally ----
        int a_prev = (t == 0) ? BB : g_active[t - 1];
        if (t == 0) {
            float4 v = *(const float4*)&h0[(size_t)pa_b * HH + pa_j4];
            __stcg((float4*)&g_hcur[pa_r][pa_j4], v);
        } else if (pa_r < a_prev) {
            float4 s = *(const float4*)&g_bias[pa_j4];
            #pragma unroll
            for (int zp = 0; zp < NS; ++zp) {
                float4 p = __ldcg((const float4*)&g_part[zp][pa_r][pa_j4]);
                s.x += p.x; s.y += p.y; s.z += p.z; s.w += p.w;
            }
            float4 v;
            v.x = tanhf(s.x); v.y = tanhf(s.y); v.z = tanhf(s.z); v.w = tanhf(s.w);
            *(float4*)&g_hout[((size_t)pa_b * TT + (t - 1)) * HH + pa_j4] = v;
            if (t < TT) __stcg((float4*)&g_hcur[pa_r][pa_j4], v);
        }
        if (t == TT) break;

        gsync(++bar);   // h(t-1) visible everywhere

        int a = g_active[t];
        if (a == 0) break;   // uniform across CTAs; all hout already written

        // ---- phase B: GEMM slice -> partials for h_t ----
        if (r0 < a) {
            // stage s_h (1536 float4, 6/thread)
            #pragma unroll
            for (int q = 0; q < 6; ++q) {
                int i  = tid + q * 256;
                int rl = i / 48;
                int kl = (i % 48) * 4;
                int r  = r0 + rl;
                int kg = z * KS + kl;
                float4 v;
                if (r >= a) {
                    v.x = v.y = v.z = v.w = 0.f;
                } else if (kg < HH) {
                    v = __ldcg((const float4*)&g_hcur[r][kg]);
                } else {
                    v = *(const float4*)&x[((size_t)s_b[rl] * TT + t) * II + (kg - HH)];
                }
                *(float4*)&s_h[rl * KS + kl] = v;
            }
            __syncthreads();

#if F32X2_OK
            unsigned long long acc2[4][2];
            #pragma unroll
            for (int i = 0; i < 4; ++i) { acc2[i][0] = 0ull; acc2[i][1] = 0ull; }
#else
            float acc[4][4];
            #pragma unroll
            for (int i = 0; i < 4; ++i)
                #pragma unroll
                for (int jj = 0; jj < 4; ++jj) acc[i][jj] = 0.f;
#endif
            #pragma unroll 6
            for (int k4 = 0; k4 < KS / 4; ++k4) {
                float4 hv[4];
                #pragma unroll
                for (int i = 0; i < 4; ++i)
                    hv[i] = *(const float4*)&s_h[(4 * ty + i) * KS + k4 * 4];
                #pragma unroll
                for (int kk = 0; kk < 4; ++kk) {
#if F32X2_OK
                    const unsigned long long* wp =
                        (const unsigned long long*)&s_w[k4 * 4 + kk][cb];
                    unsigned long long w01 = wp[0];
                    unsigned long long w23 = wp[1];
                    #pragma unroll
                    for (int i = 0; i < 4; ++i) {
                        float hh = (kk == 0) ? hv[i].x : (kk == 1) ? hv[i].y
                                 : (kk == 2) ? hv[i].z : hv[i].w;
                        unsigned long long h2 = packdup(hh);
                        fma2(acc2[i][0], h2, w01);
                        fma2(acc2[i][1], h2, w23);
                    }
#else
                    float4 wv = *(const float4*)&s_w[k4 * 4 + kk][cb];
                    #pragma unroll
                    for (int i = 0; i < 4; ++i) {
                        float hh = (kk == 0) ? hv[i].x : (kk == 1) ? hv[i].y
                                 : (kk == 2) ? hv[i].z : hv[i].w;
                        acc[i][0] = fmaf(hh, wv.x, acc[i][0]);
                        acc[i][1] = fmaf(hh, wv.y, acc[i][1]);
                        acc[i][2] = fmaf(hh, wv.z, acc[i][2]);
                        acc[i][3] = fmaf(hh, wv.w, acc[i][3]);
                    }
#endif
                }
            }

            int j = j0 + cb;
            #pragma unroll
            for (int i = 0; i < 4; ++i) {
                int r = r0 + 4 * ty + i;
                if (r >= a) continue;
                float4 v;
#if F32X2_OK
                unpack2(acc2[i][0], v.x, v.y);
                unpack2(acc2[i][1], v.z, v.w);
#else
                v = make_float4(acc[i][0], acc[i][1], acc[i][2], acc[i][3]);
#endif
                __stcg((float4*)&g_part[z][r][j], v);
            }
        }

        gsync(++bar);   // partials(t) complete before phase A(t+1) reads them
    }
}

// ---------------- FC head ----------------
__global__ __launch_bounds__(256) void fc_kernel(const int* __restrict__ lengths,
                                                 const float* __restrict__ W_fc,
                                                 const float* __restrict__ b_fc,
                                                 float* __restrict__ out,
                                                 int write_len_tail) {
    __shared__ float s_w[AA][HH];
    __shared__ float s_bias[AA];
    int tid = threadIdx.x;
    for (int i = tid; i < AA * HH; i += 256) s_w[i / HH][i % HH] = W_fc[i];
    if (tid < AA) s_bias[tid] = b_fc[tid];
    __syncthreads();

    int lane = tid & 31, wid = tid >> 5;
    int gw = blockIdx.x * 8 + wid;
    int nw = gridDim.x * 8;
    float myb = s_bias[lane < AA ? lane : 0];

    for (int item = gw; item < BB * TT; item += nw) {
        int b = item / TT, t = item % TT;
        int len = __ldg(&lengths[b]);
        float res;
        if (t < len) {
            const float4* hp = (const float4*)&g_hout[(size_t)item * HH];
            float4 h[4];
            #pragma unroll
            for (int q = 0; q < 4; ++q) h[q] = hp[q * 32 + lane];
            float myval = 0.f;
            #pragma unroll
            for (int a = 0; a < AA; ++a) {
                const float4* wp = (const float4*)&s_w[a][0];
                float p = 0.f;
                #pragma unroll
                for (int q = 0; q < 4; ++q) {
                    float4 w = wp[q * 32 + lane];
                    p = fmaf(h[q].x, w.x, p); p = fmaf(h[q].y, w.y, p);
                    p = fmaf(h[q].z, w.z, p); p = fmaf(h[q].w, w.w, p);
                }
                p += __shfl_xor_sync(0xFFFFFFFFu, p, 16);
                p += __shfl_xor_sync(0xFFFFFFFFu, p, 8);
                p += __shfl_xor_sync(0xFFFFFFFFu, p, 4);
                p += __shfl_xor_sync(0xFFFFFFFFu, p, 2);
                p += __shfl_xor_sync(0xFFFFFFFFu, p, 1);
                if (lane == a) myval = p;
            }
            res = myval + myb;
        } else {
            res = myb;
        }
        if (lane < AA) out[(size_t)item * AA + lane] = res;
    }

    if (write_len_tail && blockIdx.x == 0 && tid < BB) {
        out[(size_t)BB * TT * AA + tid] = (float)__ldg(&lengths[tid]);
    }
}

// ---------------- launch ----------------
extern "C" void kernel_launch(void* const* d_in, const int* in_sizes, int n_in,
                              void* d_out, int out_size) {
    const float* x      = (const float*)d_in[0];
    const float* h0     = (const float*)d_in[1];
    const int*   lengths= (const int*)  d_in[2];
    const float* W_ih   = (const float*)d_in[3];
    const float* W_hh   = (const float*)d_in[4];
    const float* b_ih   = (const float*)d_in[5];
    const float* b_hh   = (const float*)d_in[6];
    const float* W_fc   = (const float*)d_in[7];
    const float* b_fc   = (const float*)d_in[8];
    float* out = (float*)d_out;

    const int smem_bytes = RT * KS * 4 + KS * JT * 4;   // 24576 + 98304 = 122880
    cudaFuncSetAttribute(rnn_persist, cudaFuncAttributeMaxDynamicSharedMemorySize, smem_bytes);

    prep_sort<<<1, 512>>>(lengths);
    prep_pack<<<512, 256>>>(W_ih, W_hh, b_ih, b_hh);

    rnn_persist<<<NCTA, 256, smem_bytes>>>(x, h0);

    int tail = (out_size >= BB * TT * AA + BB) ? 1 : 0;
    fc_kernel<<<512, 256>>>(lengths, W_fc, b_fc, out, tail);
}

// round 16
// speedup vs baseline: 1.0454x; 1.0454x over previous
#include <cuda_runtime.h>
#include <math.h>

#if defined(__CUDA_ARCH_FEAT_SM103_ALL) || defined(__CUDA_ARCH_FEAT_SM100_ALL) || defined(__CUDA_ARCH_SPECIFIC__)
#define F32X2_OK 1
#else
#define F32X2_OK 0
#endif

#define BB 256
#define TT 512
#define II 256
#define HH 512
#define AA 18
#define KK 768
#define NS 8            // k slices
#define KS 96           // k per slice (48 k-pairs)
#define JT 128          // cols per CTA
#define RT 32           // rows per CTA

// ---------------- scratch (static device globals; no allocation) ----------------
__device__ float2 g_Wp[(size_t)(KK / 2) * HH];     // k-pair-interleaved: g_Wp[kp*HH + j] = (Wcat[2kp][j], Wcat[2kp+1][j])
__device__ float g_bias[HH];
__device__ float g_part[2][NS][BB][HH];            // per-slice partial pre-activations (parity buffered)
__device__ float g_hout[(size_t)BB * TT * HH];
__device__ int   g_perm[BB];
__device__ int   g_active[TT];

// ---------------- cp.async ----------------
__device__ __forceinline__ void cpa16(void* sdst, const void* gsrc) {
    unsigned s = (unsigned)__cvta_generic_to_shared(sdst);
    asm volatile("cp.async.cg.shared.global [%0], [%1], 16;\n" :: "r"(s), "l"(gsrc));
}
#define CPA_COMMIT() asm volatile("cp.async.commit_group;\n" ::: "memory")
#define CPA_WAIT0()  asm volatile("cp.async.wait_group 0;\n" ::: "memory")

// ---------------- f32x2 packed FMA (sm_103a pass only) ----------------
#if F32X2_OK
__device__ __forceinline__ void fma2(unsigned long long& d, unsigned long long a, unsigned long long b) {
    asm("fma.rn.f32x2 %0, %1, %2, %0;" : "+l"(d) : "l"(a), "l"(b));
}
__device__ __forceinline__ void unpack2(unsigned long long v, float& lo, float& hi) {
    unsigned a, b;
    asm("mov.b64 {%0, %1}, %2;" : "=r"(a), "=r"(b) : "l"(v));
    lo = __uint_as_float(a); hi = __uint_as_float(b);
}
#endif

// ---------------- prep: counting sort by length (desc) + active counts ----------------
__global__ void prep_sort(const int* __restrict__ lengths) {
    __shared__ int s_len[BB];
    __shared__ int s_hist[TT + 1];
    __shared__ int s_S[TT + 1];
    __shared__ int s_base[TT + 1];
    int tid = threadIdx.x;          // 512 threads
    if (tid < BB) s_len[tid] = lengths[tid];
    for (int i = tid; i <= TT; i += blockDim.x) s_hist[i] = 0;
    __syncthreads();
    if (tid < BB) atomicAdd(&s_hist[s_len[tid]], 1);
    __syncthreads();
    if (tid == 0) {
        s_S[TT] = 0;
        for (int v = TT - 1; v >= 0; --v) s_S[v] = s_S[v + 1] + s_hist[v + 1];
    }
    __syncthreads();
    for (int i = tid; i <= TT; i += blockDim.x) s_base[i] = s_S[i];
    if (tid < TT) g_active[tid] = s_S[tid];
    __syncthreads();
    if (tid < BB) {
        int pos = atomicAdd(&s_base[s_len[tid]], 1);
        g_perm[pos] = tid;
    }
}

// ---------------- prep: pack W into k-pair-interleaved layout + bias ----------------
__global__ void prep_pack(const float* __restrict__ W_ih, const float* __restrict__ W_hh,
                          const float* __restrict__ b_ih, const float* __restrict__ b_hh) {
    int idx = blockIdx.x * blockDim.x + threadIdx.x;
    int stride = gridDim.x * blockDim.x;
    for (int i = idx; i < (KK / 2) * HH; i += stride) {
        int kp = i / HH, j = i % HH;
        int k0 = 2 * kp, k1 = 2 * kp + 1;
        float w0 = (k0 < HH) ? W_hh[(size_t)j * HH + k0] : W_ih[(size_t)j * II + (k0 - HH)];
        float w1 = (k1 < HH) ? W_hh[(size_t)j * HH + k1] : W_ih[(size_t)j * II + (k1 - HH)];
        g_Wp[i] = make_float2(w0, w1);
    }
    for (int i = idx; i < HH; i += stride) g_bias[i] = b_ih[i] + b_hh[i];
}

// ---------------- step kernel ----------------
// kernel(t): stage h_{t-1} from partials (tanh, +g_hout[t-1] writeout), GEMM slice -> partials for h_t.
// t == TT: finalize-only pass (writes g_hout[TT-1]).
// grid: (HH/JT=4, BB/RT=8, NS=8) = 256 CTAs, 256 threads, 60KB smem -> 2 CTAs/SM.
__global__ __launch_bounds__(256, 2) void step_kernel(const float* __restrict__ x,
                                                      const float* __restrict__ h0,
                                                      int t) {
    int a_prev = (t == 0) ? BB : g_active[t - 1];
    int r0 = blockIdx.y * RT;
    if (r0 >= a_prev) return;
    int z  = blockIdx.z;
    int cg = blockIdx.x;
    int j0 = cg * JT;
    int tid = threadIdx.x;
    int pbR = (t & 1) ^ 1;   // partials written by step t-1
    int pbW = t & 1;

    __shared__ int s_b[RT];
    if (tid < RT) s_b[tid] = g_perm[r0 + tid];

    const int KS4 = KS / 4;   // 24

    // ---- finalize-only pass ----
    if (t == TT) {
        __syncthreads();
        if (cg != 0 || z >= 6) return;
        for (int i4 = tid; i4 < RT * KS4; i4 += 256) {
            int rl = i4 / KS4;
            int kl = (i4 % KS4) * 4;
            int r  = r0 + rl;
            int kg = z * KS + kl;
            if (r >= a_prev || kg >= HH) continue;
            float4 v = *(const float4*)&g_part[pbR][0][r][kg];
            #pragma unroll
            for (int zp = 1; zp < NS; ++zp) {
                float4 p = *(const float4*)&g_part[pbR][zp][r][kg];
                v.x += p.x; v.y += p.y; v.z += p.z; v.w += p.w;
            }
            v.x = tanhf(v.x); v.y = tanhf(v.y); v.z = tanhf(v.z); v.w = tanhf(v.w);
            *(float4*)&g_hout[((size_t)s_b[rl] * TT + (TT - 1)) * HH + kg] = v;
        }
        return;
    }

    extern __shared__ char smem_raw[];
    float  (*s_h)[KS] = (float  (*)[KS])smem_raw;                  // 32 x 96 floats = 12 KB
    float2 (*s_w)[JT] = (float2 (*)[JT])(smem_raw + RT * KS * 4);  // 48 x 128 float2 = 48 KB

    // issue the WHOLE paired-W slice via cp.async (3072 x 16B, 12/thread)
    {
        const float2* gw = g_Wp + (size_t)(z * (KS / 2)) * HH + j0;
        #pragma unroll
        for (int q = 0; q < 12; ++q) {
            int p   = tid + q * 256;       // 0..3071
            int kp  = p >> 6;              // 0..47
            int c2  = (p & 63) * 2;        // float2 col pairs
            cpa16(&s_w[kp][c2], gw + (size_t)kp * HH + c2);
        }
        CPA_COMMIT();
    }
    __syncthreads();   // s_b visible

    // ---- stage s_h: h part = tanh(sum of NS partials); x part from gmem ----
    for (int i4 = tid; i4 < RT * KS4; i4 += 256) {
        int rl = i4 / KS4;
        int kl = (i4 % KS4) * 4;
        int r  = r0 + rl;
        int kg = z * KS + kl;
        float4 v;
        if (r >= a_prev) {
            v.x = v.y = v.z = v.w = 0.f;
        } else if (kg < HH) {
            if (t == 0) {
                v = *(const float4*)&h0[(size_t)s_b[rl] * HH + kg];
            } else {
                v = *(const float4*)&g_part[pbR][0][r][kg];
                #pragma unroll
                for (int zp = 1; zp < NS; ++zp) {
                    float4 p = *(const float4*)&g_part[pbR][zp][r][kg];
                    v.x += p.x; v.y += p.y; v.z += p.z; v.w += p.w;
                }
                v.x = tanhf(v.x); v.y = tanhf(v.y); v.z = tanhf(v.z); v.w = tanhf(v.w);
                if (cg == 0)
                    *(float4*)&g_hout[((size_t)s_b[rl] * TT + (t - 1)) * HH + kg] = v;
            }
        } else {
            v = *(const float4*)&x[((size_t)s_b[rl] * TT + t) * II + (kg - HH)];
        }
        *(float4*)&s_h[rl][kl] = v;
    }

    CPA_WAIT0();
    __syncthreads();   // s_h + s_w ready — single barrier for the whole step

    // ---- GEMM: 32x128 tile, 4 rows x 4 cols per thread, k-pair interleaved ----
    int ty = tid >> 5;          // 0..7 (row group of 4)
    int tx = tid & 31;          // 0..31 (col group of 4)
    int cb = tx * 4;

#if F32X2_OK
    unsigned long long acc[4][4];   // acc[row][col]: .lo = even-k sum, .hi = odd-k sum
    #pragma unroll
    for (int i = 0; i < 4; ++i)
        #pragma unroll
        for (int c = 0; c < 4; ++c) acc[i][c] = 0ull;

    #pragma unroll 8
    for (int kp = 0; kp < KS / 2; ++kp) {
        const ulonglong2* wp = (const ulonglong2*)&s_w[kp][cb];
        ulonglong2 wA = wp[0];   // cols cb, cb+1
        ulonglong2 wB = wp[1];   // cols cb+2, cb+3
        #pragma unroll
        for (int i = 0; i < 4; ++i) {
            unsigned long long h2 =
                *(const unsigned long long*)&s_h[4 * ty + i][2 * kp];
            fma2(acc[i][0], h2, wA.x);
            fma2(acc[i][1], h2, wA.y);
            fma2(acc[i][2], h2, wB.x);
            fma2(acc[i][3], h2, wB.y);
        }
    }
#else
    float acc[4][4];
    #pragma unroll
    for (int i = 0; i < 4; ++i)
        #pragma unroll
        for (int c = 0; c < 4; ++c) acc[i][c] = 0.f;

    #pragma unroll 8
    for (int kp = 0; kp < KS / 2; ++kp) {
        float4 wA = *(const float4*)&s_w[kp][cb];       // (w_e[cb], w_o[cb], w_e[cb+1], w_o[cb+1])
        float4 wB = *(const float4*)&s_w[kp][cb + 2];
        #pragma unroll
        for (int i = 0; i < 4; ++i) {
            float2 h2 = *(const float2*)&s_h[4 * ty + i][2 * kp];
            acc[i][0] = fmaf(h2.x, wA.x, fmaf(h2.y, wA.y, acc[i][0]));
            acc[i][1] = fmaf(h2.x, wA.z, fmaf(h2.y, wA.w, acc[i][1]));
            acc[i][2] = fmaf(h2.x, wB.x, fmaf(h2.y, wB.y, acc[i][2]));
            acc[i][3] = fmaf(h2.x, wB.z, fmaf(h2.y, wB.w, acc[i][3]));
        }
    }
#endif

    // ---- epilogue: write slice partials (bias folded into slice 0) ----
    int j = j0 + cb;
    float4 bv = make_float4(0.f, 0.f, 0.f, 0.f);
    if (z == 0) bv = *(const float4*)&g_bias[j];
    #pragma unroll
    for (int i = 0; i < 4; ++i) {
        int r = r0 + 4 * ty + i;
        float4 v;
#if F32X2_OK
        float e0, o0, e1, o1, e2, o2, e3, o3;
        unpack2(acc[i][0], e0, o0);
        unpack2(acc[i][1], e1, o1);
        unpack2(acc[i][2], e2, o2);
        unpack2(acc[i][3], e3, o3);
        v = make_float4(e0 + o0, e1 + o1, e2 + o2, e3 + o3);
#else
        v = make_float4(acc[i][0], acc[i][1], acc[i][2], acc[i][3]);
#endif
        v.x += bv.x; v.y += bv.y; v.z += bv.z; v.w += bv.w;
        *(float4*)&g_part[pbW][z][r][j] = v;
    }
}

// ---------------- FC head ----------------
__global__ __launch_bounds__(256) void fc_kernel(const int* __restrict__ lengths,
                                                 const float* __restrict__ W_fc,
                                                 const float* __restrict__ b_fc,
                                                 float* __restrict__ out,
                                                 int write_len_tail) {
    __shared__ float s_w[AA][HH];
    __shared__ float s_bias[AA];
    int tid = threadIdx.x;
    for (int i = tid; i < AA * HH; i += 256) s_w[i / HH][i % HH] = W_fc[i];
    if (tid < AA) s_bias[tid] = b_fc[tid];
    __syncthreads();

    int lane = tid & 31, wid = tid >> 5;
    int gw = blockIdx.x * 8 + wid;
    int nw = gridDim.x * 8;
    float myb = s_bias[lane < AA ? lane : 0];

    for (int item = gw; item < BB * TT; item += nw) {
        int b = item / TT, t = item % TT;
        int len = __ldg(&lengths[b]);
        float res;
        if (t < len) {
            const float4* hp = (const float4*)&g_hout[(size_t)item * HH];
            float4 h[4];
            #pragma unroll
            for (int q = 0; q < 4; ++q) h[q] = hp[q * 32 + lane];
            float myval = 0.f;
            #pragma unroll
            for (int a = 0; a < AA; ++a) {
                const float4* wp = (const float4*)&s_w[a][0];
                float p = 0.f;
                #pragma unroll
                for (int q = 0; q < 4; ++q) {
                    float4 w = wp[q * 32 + lane];
                    p = fmaf(h[q].x, w.x, p); p = fmaf(h[q].y, w.y, p);
                    p = fmaf(h[q].z, w.z, p); p = fmaf(h[q].w, w.w, p);
                }
                p += __shfl_xor_sync(0xFFFFFFFFu, p, 16);
                p += __shfl_xor_sync(0xFFFFFFFFu, p, 8);
                p += __shfl_xor_sync(0xFFFFFFFFu, p, 4);
                p += __shfl_xor_sync(0xFFFFFFFFu, p, 2);
                p += __shfl_xor_sync(0xFFFFFFFFu, p, 1);
                if (lane == a) myval = p;
            }
            res = myval + myb;
        } else {
            res = myb;
        }
        if (lane < AA) out[(size_t)item * AA + lane] = res;
    }

    if (write_len_tail && blockIdx.x == 0 && tid < BB) {
        out[(size_t)BB * TT * AA + tid] = (float)__ldg(&lengths[tid]);
    }
}

// ---------------- launch ----------------
extern "C" void kernel_launch(void* const* d_in, const int* in_sizes, int n_in,
                              void* d_out, int out_size) {
    const float* x      = (const float*)d_in[0];
    const float* h0     = (const float*)d_in[1];
    const int*   lengths= (const int*)  d_in[2];
    const float* W_ih   = (const float*)d_in[3];
    const float* W_hh   = (const float*)d_in[4];
    const float* b_ih   = (const float*)d_in[5];
    const float* b_hh   = (const float*)d_in[6];
    const float* W_fc   = (const float*)d_in[7];
    const float* b_fc   = (const float*)d_in[8];
    float* out = (float*)d_out;

    const int smem_bytes = RT * KS * 4 + (KS / 2) * JT * 8;   // 12KB + 48KB = 61440
    cudaFuncSetAttribute(step_kernel, cudaFuncAttributeMaxDynamicSharedMemorySize, smem_bytes);

    prep_sort<<<1, 512>>>(lengths);
    prep_pack<<<512, 256>>>(W_ih, W_hh, b_ih, b_hh);

    dim3 grid(HH / JT, BB / RT, NS);   // (4, 8, 8) = 256 CTAs
    for (int t = 0; t <= TT; ++t) {
        step_kernel<<<grid, 256, smem_bytes>>>(x, h0, t);
    }

    int tail = (out_size >= BB * TT * AA + BB) ? 1 : 0;
    fc_kernel<<<512, 256>>>(lengths, W_fc, b_fc, out, tail);
}

// round 17
// speedup vs baseline: 1.3075x; 1.2508x over previous
#include <cuda_runtime.h>
#include <math.h>

#if defined(__CUDA_ARCH_FEAT_SM103_ALL) || defined(__CUDA_ARCH_FEAT_SM100_ALL) || defined(__CUDA_ARCH_SPECIFIC__)
#define F32X2_OK 1
#else
#define F32X2_OK 0
#endif

#define BB 256
#define TT 512
#define II 256
#define HH 512
#define AA 18
#define KK 768
#define NS 8            // k slices
#define KS 96           // k per slice (48 k-pairs)
#define JT 128          // cols per CTA
#define RT 32           // rows per CTA

// ---------------- scratch (static device globals; no allocation) ----------------
__device__ float2 g_Wp[(size_t)(KK / 2) * HH];     // k-pair: g_Wp[kp*HH + j] = (Wcat[2kp][j], Wcat[2kp+1][j])
__device__ float g_bias[HH];
__device__ float g_part[2][NS][BB][HH];            // per-slice partial pre-activations (parity buffered)
__device__ float g_hout[(size_t)BB * TT * HH];
__device__ int   g_perm[BB];
__device__ int   g_active[TT];

// ---------------- cp.async ----------------
__device__ __forceinline__ void cpa16(void* sdst, const void* gsrc) {
    unsigned s = (unsigned)__cvta_generic_to_shared(sdst);
    asm volatile("cp.async.cg.shared.global [%0], [%1], 16;\n" :: "r"(s), "l"(gsrc));
}
#define CPA_COMMIT() asm volatile("cp.async.commit_group;\n" ::: "memory")
#define CPA_WAIT0()  asm volatile("cp.async.wait_group 0;\n" ::: "memory")

// ---------------- f32x2 packed FMA (sm_103a pass only) ----------------
#if F32X2_OK
__device__ __forceinline__ void fma2(unsigned long long& d, unsigned long long a, unsigned long long b) {
    asm("fma.rn.f32x2 %0, %1, %2, %0;" : "+l"(d) : "l"(a), "l"(b));
}
__device__ __forceinline__ void unpack2(unsigned long long v, float& lo, float& hi) {
    unsigned a, b;
    asm("mov.b64 {%0, %1}, %2;" : "=r"(a), "=r"(b) : "l"(v));
    lo = __uint_as_float(a); hi = __uint_as_float(b);
}
#endif

// ---------------- prep: counting sort by length (desc) + active counts ----------------
__global__ void prep_sort(const int* __restrict__ lengths) {
    __shared__ int s_len[BB];
    __shared__ int s_hist[TT + 1];
    __shared__ int s_S[TT + 1];
    __shared__ int s_base[TT + 1];
    int tid = threadIdx.x;          // 512 threads
    if (tid < BB) s_len[tid] = lengths[tid];
    for (int i = tid; i <= TT; i += blockDim.x) s_hist[i] = 0;
    __syncthreads();
    if (tid < BB) atomicAdd(&s_hist[s_len[tid]], 1);
    __syncthreads();
    if (tid == 0) {
        s_S[TT] = 0;
        for (int v = TT - 1; v >= 0; --v) s_S[v] = s_S[v + 1] + s_hist[v + 1];
    }
    __syncthreads();
    for (int i = tid; i <= TT; i += blockDim.x) s_base[i] = s_S[i];
    if (tid < TT) g_active[tid] = s_S[tid];
    __syncthreads();
    if (tid < BB) {
        int pos = atomicAdd(&s_base[s_len[tid]], 1);
        g_perm[pos] = tid;
    }
}

// ---------------- prep: pack W into k-pair layout + bias ----------------
__global__ void prep_pack(const float* __restrict__ W_ih, const float* __restrict__ W_hh,
                          const float* __restrict__ b_ih, const float* __restrict__ b_hh) {
    int idx = blockIdx.x * blockDim.x + threadIdx.x;
    int stride = gridDim.x * blockDim.x;
    for (int i = idx; i < (KK / 2) * HH; i += stride) {
        int kp = i / HH, j = i % HH;
        int k0 = 2 * kp, k1 = 2 * kp + 1;
        float w0 = (k0 < HH) ? W_hh[(size_t)j * HH + k0] : W_ih[(size_t)j * II + (k0 - HH)];
        float w1 = (k1 < HH) ? W_hh[(size_t)j * HH + k1] : W_ih[(size_t)j * II + (k1 - HH)];
        g_Wp[i] = make_float2(w0, w1);
    }
    for (int i = idx; i < HH; i += stride) g_bias[i] = b_ih[i] + b_hh[i];
}

// ---------------- step kernel ----------------
// kernel(t): stage h_{t-1} from partials (tanh, +g_hout[t-1] writeout), GEMM slice -> partials for h_t.
// t == TT: finalize-only pass (writes g_hout[TT-1]).
// grid: (HH/JT=4, BB/RT=8, NS=8) = 256 CTAs, 256 threads, 60KB smem -> 2 CTAs/SM.
__global__ __launch_bounds__(256, 2) void step_kernel(const float* __restrict__ x,
                                                      const float* __restrict__ h0,
                                                      int t) {
    int a_prev = (t == 0) ? BB : g_active[t - 1];
    int r0 = blockIdx.y * RT;
    if (r0 >= a_prev) return;
    int z  = blockIdx.z;
    int cg = blockIdx.x;
    int j0 = cg * JT;
    int tid = threadIdx.x;
    int pbR = (t & 1) ^ 1;   // partials written by step t-1
    int pbW = t & 1;

    const int KS4 = KS / 4;   // 24

    // ---- finalize-only pass ----
    if (t == TT) {
        if (cg != 0 || z >= 6) return;
        for (int i4 = tid; i4 < RT * KS4; i4 += 256) {
            int rl = i4 / KS4;
            int kl = (i4 % KS4) * 4;
            int r  = r0 + rl;
            int kg = z * KS + kl;
            if (r >= a_prev || kg >= HH) continue;
            float4 v = *(const float4*)&g_part[pbR][0][r][kg];
            #pragma unroll
            for (int zp = 1; zp < NS; ++zp) {
                float4 p = *(const float4*)&g_part[pbR][zp][r][kg];
                v.x += p.x; v.y += p.y; v.z += p.z; v.w += p.w;
            }
            v.x = tanhf(v.x); v.y = tanhf(v.y); v.z = tanhf(v.z); v.w = tanhf(v.w);
            int b = __ldg(&g_perm[r]);
            *(float4*)&g_hout[((size_t)b * TT + (TT - 1)) * HH + kg] = v;
        }
        return;
    }

    extern __shared__ char smem_raw[];
    float  (*s_h)[KS] = (float  (*)[KS])smem_raw;                  // 32 x 96 floats = 12 KB
    float2 (*s_w)[JT] = (float2 (*)[JT])(smem_raw + RT * KS * 4);  // 48 x 128 float2 = 48 KB

    // issue the WHOLE paired-W slice via cp.async (3072 x 16B, 12/thread)
    {
        const float2* gw = g_Wp + (size_t)(z * (KS / 2)) * HH + j0;
        #pragma unroll
        for (int q = 0; q < 12; ++q) {
            int p   = tid + q * 256;       // 0..3071
            int kp  = p >> 6;              // 0..47
            int c2  = (p & 63) * 2;        // float2 col pairs
            cpa16(&s_w[kp][c2], gw + (size_t)kp * HH + c2);
        }
        CPA_COMMIT();
    }

    // ---- stage s_h: h part = tanh(sum of NS partials); x part from gmem ----
    for (int i4 = tid; i4 < RT * KS4; i4 += 256) {
        int rl = i4 / KS4;
        int kl = (i4 % KS4) * 4;
        int r  = r0 + rl;
        int kg = z * KS + kl;
        float4 v;
        if (r >= a_prev) {
            v.x = v.y = v.z = v.w = 0.f;
        } else if (kg < HH) {
            if (t == 0) {
                int b = __ldg(&g_perm[r]);
                v = *(const float4*)&h0[(size_t)b * HH + kg];
            } else {
                v = *(const float4*)&g_part[pbR][0][r][kg];
                #pragma unroll
                for (int zp = 1; zp < NS; ++zp) {
                    float4 p = *(const float4*)&g_part[pbR][zp][r][kg];
                    v.x += p.x; v.y += p.y; v.z += p.z; v.w += p.w;
                }
                v.x = tanhf(v.x); v.y = tanhf(v.y); v.z = tanhf(v.z); v.w = tanhf(v.w);
                if (cg == 0) {
                    int b = __ldg(&g_perm[r]);
                    *(float4*)&g_hout[((size_t)b * TT + (t - 1)) * HH + kg] = v;
                }
            }
        } else {
            int b = __ldg(&g_perm[r]);
            v = *(const float4*)&x[((size_t)b * TT + t) * II + (kg - HH)];
        }
        *(float4*)&s_h[rl][kl] = v;
    }

    CPA_WAIT0();
    __syncthreads();   // the ONLY barrier: s_h + s_w ready

    // ---- GEMM: 32x128 tile, 4 rows x 4 interleaved cols per thread, k-pair accumulators ----
    int ty = tid >> 5;          // 0..7 (row group of 4)
    int tx = tid & 31;          // col base; cols tx + 32c

#if F32X2_OK
    unsigned long long acc[4][4];   // [row][c]: .lo = even-k sum, .hi = odd-k sum
    #pragma unroll
    for (int i = 0; i < 4; ++i)
        #pragma unroll
        for (int c = 0; c < 4; ++c) acc[i][c] = 0ull;

    #pragma unroll 12
    for (int kp = 0; kp < KS / 2; ++kp) {
        unsigned long long h2[4];
        #pragma unroll
        for (int i = 0; i < 4; ++i)
            h2[i] = *(const unsigned long long*)&s_h[4 * ty + i][2 * kp];
        #pragma unroll
        for (int c = 0; c < 4; ++c) {
            unsigned long long w2 = *(const unsigned long long*)&s_w[kp][tx + 32 * c];
            fma2(acc[0][c], h2[0], w2);
            fma2(acc[1][c], h2[1], w2);
            fma2(acc[2][c], h2[2], w2);
            fma2(acc[3][c], h2[3], w2);
        }
    }
#else
    float acc[4][4];
    #pragma unroll
    for (int i = 0; i < 4; ++i)
        #pragma unroll
        for (int c = 0; c < 4; ++c) acc[i][c] = 0.f;

    #pragma unroll 12
    for (int kp = 0; kp < KS / 2; ++kp) {
        float2 h2[4];
        #pragma unroll
        for (int i = 0; i < 4; ++i)
            h2[i] = *(const float2*)&s_h[4 * ty + i][2 * kp];
        #pragma unroll
        for (int c = 0; c < 4; ++c) {
            float2 w2 = s_w[kp][tx + 32 * c];
            #pragma unroll
            for (int i = 0; i < 4; ++i)
                acc[i][c] = fmaf(h2[i].x, w2.x, fmaf(h2[i].y, w2.y, acc[i][c]));
        }
    }
#endif

    // ---- epilogue: write slice partials (bias folded into slice 0), interleaved cols ----
    float bv[4] = {0.f, 0.f, 0.f, 0.f};
    if (z == 0) {
        #pragma unroll
        for (int c = 0; c < 4; ++c) bv[c] = g_bias[j0 + tx + 32 * c];
    }
    #pragma unroll
    for (int i = 0; i < 4; ++i) {
        int r = r0 + 4 * ty + i;
        #pragma unroll
        for (int c = 0; c < 4; ++c) {
            float val;
#if F32X2_OK
            float lo, hi;
            unpack2(acc[i][c], lo, hi);
            val = lo + hi + bv[c];
#else
            val = acc[i][c] + bv[c];
#endif
            g_part[pbW][z][r][j0 + tx + 32 * c] = val;
        }
    }
}

// ---------------- FC head ----------------
__global__ __launch_bounds__(256) void fc_kernel(const int* __restrict__ lengths,
                                                 const float* __restrict__ W_fc,
                                                 const float* __restrict__ b_fc,
                                                 float* __restrict__ out,
                                                 int write_len_tail) {
    __shared__ float s_w[AA][HH];
    __shared__ float s_bias[AA];
    int tid = threadIdx.x;
    for (int i = tid; i < AA * HH; i += 256) s_w[i / HH][i % HH] = W_fc[i];
    if (tid < AA) s_bias[tid] = b_fc[tid];
    __syncthreads();

    int lane = tid & 31, wid = tid >> 5;
    int gw = blockIdx.x * 8 + wid;
    int nw = gridDim.x * 8;
    float myb = s_bias[lane < AA ? lane : 0];

    for (int item = gw; item < BB * TT; item += nw) {
        int b = item / TT, t = item % TT;
        int len = __ldg(&lengths[b]);
        float res;
        if (t < len) {
            const float4* hp = (const float4*)&g_hout[(size_t)item * HH];
            float4 h[4];
            #pragma unroll
            for (int q = 0; q < 4; ++q) h[q] = hp[q * 32 + lane];
            float myval = 0.f;
            #pragma unroll
            for (int a = 0; a < AA; ++a) {
                const float4* wp = (const float4*)&s_w[a][0];
                float p = 0.f;
                #pragma unroll
                for (int q = 0; q < 4; ++q) {
                    float4 w = wp[q * 32 + lane];
                    p = fmaf(h[q].x, w.x, p); p = fmaf(h[q].y, w.y, p);
                    p = fmaf(h[q].z, w.z, p); p = fmaf(h[q].w, w.w, p);
                }
                p += __shfl_xor_sync(0xFFFFFFFFu, p, 16);
                p += __shfl_xor_sync(0xFFFFFFFFu, p, 8);
                p += __shfl_xor_sync(0xFFFFFFFFu, p, 4);
                p += __shfl_xor_sync(0xFFFFFFFFu, p, 2);
                p += __shfl_xor_sync(0xFFFFFFFFu, p, 1);
                if (lane == a) myval = p;
            }
            res = myval + myb;
        } else {
            res = myb;
        }
        if (lane < AA) out[(size_t)item * AA + lane] = res;
    }

    if (write_len_tail && blockIdx.x == 0 && tid < BB) {
        out[(size_t)BB * TT * AA + tid] = (float)__ldg(&lengths[tid]);
    }
}

// ---------------- launch ----------------
extern "C" void kernel_launch(void* const* d_in, const int* in_sizes, int n_in,
                              void* d_out, int out_size) {
    const float* x      = (const float*)d_in[0];
    const float* h0     = (const float*)d_in[1];
    const int*   lengths= (const int*)  d_in[2];
    const float* W_ih   = (const float*)d_in[3];
    const float* W_hh   = (const float*)d_in[4];
    const float* b_ih   = (const float*)d_in[5];
    const float* b_hh   = (const float*)d_in[6];
    const float* W_fc   = (const float*)d_in[7];
    const float* b_fc   = (const float*)d_in[8];
    float* out = (float*)d_out;

    const int smem_bytes = RT * KS * 4 + (KS / 2) * JT * 8;   // 12KB + 48KB = 61440
    cudaFuncSetAttribute(step_kernel, cudaFuncAttributeMaxDynamicSharedMemorySize, smem_bytes);

    prep_sort<<<1, 512>>>(lengths);
    prep_pack<<<512, 256>>>(W_ih, W_hh, b_ih, b_hh);

    dim3 grid(HH / JT, BB / RT, NS);   // (4, 8, 8) = 256 CTAs
    for (int t = 0; t <= TT; ++t) {
        step_kernel<<<grid, 256, smem_bytes>>>(x, h0, t);
    }

    int tail = (out_size >= BB * TT * AA + BB) ? 1 : 0;
    fc_kernel<<<512, 256>>>(lengths, W_fc, b_fc, out, tail);
}